// round 12
// baseline (speedup 1.0000x reference)
#include <cuda_runtime.h>
#include <cstdint>

#define BB 2
#define LL 256
#define HH 512
#define NHH 8
#define DHH 64

// ---------------- scratch (device globals; no allocation) ----------------
__device__ __align__(16) float g_K[BB*LL*HH];
__device__ __align__(16) float g_Q[BB*LL*HH];
__device__ __align__(16) float g_V[BB*LL*HH];
__device__ __align__(16) float g_T[BB*LL*NHH*HH];    // [m][n][h]  8 MB
__device__ __align__(16) float g_AC[BB*LL*NHH*LL];   // [m][n][j]  4 MB
__device__ __align__(16) float g_P[BB*LL*NHH*LL];    // [m][n][j]  4 MB
__device__ __align__(16) float g_CTX[BB*LL*HH];

// ---------------- f32x2 helpers ----------------
__device__ __forceinline__ unsigned long long ffma2(unsigned long long a,
                                                    unsigned long long b,
                                                    unsigned long long c) {
    unsigned long long d;
    asm("fma.rn.f32x2 %0, %1, %2, %3;" : "=l"(d) : "l"(a), "l"(b), "l"(c));
    return d;
}
__device__ __forceinline__ unsigned long long splat2(float a) {
    unsigned long long r;
    asm("mov.b64 %0, {%1, %1};" : "=l"(r) : "f"(a));
    return r;
}
__device__ __forceinline__ float2 unpack2(unsigned long long v) {
    float2 f;
    asm("mov.b64 {%0, %1}, %2;" : "=f"(f.x), "=f"(f.y) : "l"(v));
    return f;
}
__device__ __forceinline__ void cpasync16(uint32_t s, const void* g) {
    asm volatile("cp.async.cg.shared.global [%0], [%1], 16;\n" :: "r"(s), "l"(g));
}
__device__ __forceinline__ void cpasync_commit() {
    asm volatile("cp.async.commit_group;\n" ::: "memory");
}
template <int N>
__device__ __forceinline__ void cpasync_wait() {
    asm volatile("cp.async.wait_group %0;\n" :: "n"(N) : "memory");
}

// ---------------- 32x64-tile GEMM, 128 threads, 4x4 microtile ----------------
__device__ __forceinline__ void gemm32x64_body(const float* __restrict__ A,
                                               const float* __restrict__ W,
                                               const float* __restrict__ bias,
                                               float* __restrict__ C)
{
    __shared__ __align__(16) float As[32][36];   // [k][m]
    __shared__ __align__(16) float Bs[32][68];   // [k][n]

    const int tid = threadIdx.x;        // 0..127
    const int tx  = tid & 15;
    const int ty  = tid >> 4;
    const int row0 = blockIdx.y * 32;
    const int col0 = blockIdx.x * 64;

    const int lm = tid >> 2;            // A row 0..31
    const int lk = (tid & 3) * 8;       // A k offset
    const int brr = tid >> 4;           // B base row 0..7
    const int bc  = (tid & 15) * 4;     // B col offset

    float4 a0 = *(const float4*)&A[(row0 + lm) * 512 + lk];
    float4 a1 = *(const float4*)&A[(row0 + lm) * 512 + lk + 4];
    float4 b0 = *(const float4*)&W[(brr +  0) * 512 + col0 + bc];
    float4 b1 = *(const float4*)&W[(brr +  8) * 512 + col0 + bc];
    float4 b2 = *(const float4*)&W[(brr + 16) * 512 + col0 + bc];
    float4 b3 = *(const float4*)&W[(brr + 24) * 512 + col0 + bc];

    unsigned long long acc[4][2] = {};

    for (int kt = 0; kt < 512; kt += 32) {
        As[lk + 0][lm] = a0.x; As[lk + 1][lm] = a0.y;
        As[lk + 2][lm] = a0.z; As[lk + 3][lm] = a0.w;
        As[lk + 4][lm] = a1.x; As[lk + 5][lm] = a1.y;
        As[lk + 6][lm] = a1.z; As[lk + 7][lm] = a1.w;
        *(float4*)&Bs[brr +  0][bc] = b0;
        *(float4*)&Bs[brr +  8][bc] = b1;
        *(float4*)&Bs[brr + 16][bc] = b2;
        *(float4*)&Bs[brr + 24][bc] = b3;
        __syncthreads();

        if (kt + 32 < 512) {
            a0 = *(const float4*)&A[(row0 + lm) * 512 + kt + 32 + lk];
            a1 = *(const float4*)&A[(row0 + lm) * 512 + kt + 32 + lk + 4];
            b0 = *(const float4*)&W[(kt + 32 + brr +  0) * 512 + col0 + bc];
            b1 = *(const float4*)&W[(kt + 32 + brr +  8) * 512 + col0 + bc];
            b2 = *(const float4*)&W[(kt + 32 + brr + 16) * 512 + col0 + bc];
            b3 = *(const float4*)&W[(kt + 32 + brr + 24) * 512 + col0 + bc];
        }

        #pragma unroll
        for (int kk = 0; kk < 32; kk++) {
            float4 av = *(const float4*)&As[kk][ty * 4];
            ulonglong2 bp = *(const ulonglong2*)&Bs[kk][tx * 4];
            unsigned long long s0 = splat2(av.x);
            unsigned long long s1 = splat2(av.y);
            unsigned long long s2 = splat2(av.z);
            unsigned long long s3 = splat2(av.w);
            acc[0][0] = ffma2(s0, bp.x, acc[0][0]); acc[0][1] = ffma2(s0, bp.y, acc[0][1]);
            acc[1][0] = ffma2(s1, bp.x, acc[1][0]); acc[1][1] = ffma2(s1, bp.y, acc[1][1]);
            acc[2][0] = ffma2(s2, bp.x, acc[2][0]); acc[2][1] = ffma2(s2, bp.y, acc[2][1]);
            acc[3][0] = ffma2(s3, bp.x, acc[3][0]); acc[3][1] = ffma2(s3, bp.y, acc[3][1]);
        }
        __syncthreads();
    }

    float4 bb = *(const float4*)&bias[col0 + tx * 4];
    #pragma unroll
    for (int r = 0; r < 4; r++) {
        float2 p0 = unpack2(acc[r][0]);
        float2 p1 = unpack2(acc[r][1]);
        float4 o;
        o.x = p0.x + bb.x; o.y = p0.y + bb.y;
        o.z = p1.x + bb.z; o.w = p1.y + bb.w;
        *(float4*)&C[(row0 + ty * 4 + r) * 512 + col0 + tx * 4] = o;
    }
}

__global__ void proj_kernel(const float* __restrict__ key,
                            const float* __restrict__ query,
                            const float* __restrict__ value,
                            const float* __restrict__ Wk, const float* __restrict__ bk,
                            const float* __restrict__ Wq, const float* __restrict__ bq,
                            const float* __restrict__ Wv, const float* __restrict__ bv)
{
    const float *A, *W, *bias;
    float* C;
    if (blockIdx.z == 0)      { A = key;   W = Wk; bias = bk; C = g_K; }
    else if (blockIdx.z == 1) { A = query; W = Wq; bias = bq; C = g_Q; }
    else                      { A = value; W = Wv; bias = bv; C = g_V; }
    gemm32x64_body(A, W, bias, C);
}

__global__ void final_kernel(const float* __restrict__ Wf,
                             const float* __restrict__ bf,
                             float* __restrict__ out)
{
    gemm32x64_body(g_CTX, Wf, bf, out);
}

// ---------------- K=64 A@B^T body (tilde + AC), register-prefetched ----------------
__device__ __forceinline__ void nt64_body(const float* __restrict__ Arow0,
                                          const float* __restrict__ avec,
                                          const float* __restrict__ Brow0,
                                          float* __restrict__ Cbase, int ldc)
{
    __shared__ __align__(16) float As[16][68];
    __shared__ __align__(16) float Bs[16][68];

    const int tid = threadIdx.x;
    const int tx = tid & 15, ty = tid >> 4;
    const int lm = tid >> 2;
    const int lk = (tid & 3) * 4;

    unsigned long long acc[4][2] = {};

    float4 a_n = *(const float4*)&Arow0[lm * 512 + lk];
    float4 b_n = *(const float4*)&Brow0[lm * 512 + lk];

    for (int kt = 0; kt < 64; kt += 16) {
        float4 vb = *(const float4*)&avec[kt + lk];
        As[lk + 0][lm] = a_n.x + vb.x; As[lk + 1][lm] = a_n.y + vb.y;
        As[lk + 2][lm] = a_n.z + vb.z; As[lk + 3][lm] = a_n.w + vb.w;
        Bs[lk + 0][lm] = b_n.x; Bs[lk + 1][lm] = b_n.y;
        Bs[lk + 2][lm] = b_n.z; Bs[lk + 3][lm] = b_n.w;
        __syncthreads();

        if (kt + 16 < 64) {
            a_n = *(const float4*)&Arow0[lm * 512 + kt + 16 + lk];
            b_n = *(const float4*)&Brow0[lm * 512 + kt + 16 + lk];
        }

        #pragma unroll
        for (int kk = 0; kk < 16; kk++) {
            float4 av = *(const float4*)&As[kk][ty * 4];
            ulonglong2 bp = *(const ulonglong2*)&Bs[kk][tx * 4];
            unsigned long long s0 = splat2(av.x);
            unsigned long long s1 = splat2(av.y);
            unsigned long long s2 = splat2(av.z);
            unsigned long long s3 = splat2(av.w);
            acc[0][0] = ffma2(s0, bp.x, acc[0][0]); acc[0][1] = ffma2(s0, bp.y, acc[0][1]);
            acc[1][0] = ffma2(s1, bp.x, acc[1][0]); acc[1][1] = ffma2(s1, bp.y, acc[1][1]);
            acc[2][0] = ffma2(s2, bp.x, acc[2][0]); acc[2][1] = ffma2(s2, bp.y, acc[2][1]);
            acc[3][0] = ffma2(s3, bp.x, acc[3][0]); acc[3][1] = ffma2(s3, bp.y, acc[3][1]);
        }
        __syncthreads();
    }

    #pragma unroll
    for (int r = 0; r < 4; r++) {
        float2 p0 = unpack2(acc[r][0]);
        float2 p1 = unpack2(acc[r][1]);
        float4 o; o.x = p0.x; o.y = p0.y; o.z = p1.x; o.w = p1.y;
        *(float4*)&Cbase[(ty * 4 + r) * ldc + tx * 4] = o;
    }
}

// tilde (bid<512): T[m][n][h] = sum_d (Q[m][n*64+d]+vpos[n*64+d]) * Wr[h][n*64+d]
// ac (bid>=512):   AC[m][n][j] = sum_d (Q[m][n*64+d]+upos[n*64+d]) * K[b][j][n*64+d]
__global__ void tac_kernel(const float* __restrict__ Wr,
                           const float* __restrict__ vpos,
                           const float* __restrict__ upos)
{
    const int bid = blockIdx.x;
    if (bid < 512) {
        const int n    = bid >> 6;
        const int rest = bid & 63;
        const int h0   = (rest & 7) * 64;
        const int m0   = (rest >> 3) * 64;
        nt64_body(g_Q + m0 * 512 + n * 64, vpos + n * 64,
                  Wr + h0 * 512 + n * 64,
                  g_T + (m0 * 8 + n) * 512 + h0, 4096);
    } else {
        const int r    = bid - 512;
        const int n    = r >> 5;
        const int rest = r & 31;
        const int j0   = (rest & 3) * 64;
        const int q    = rest >> 2;          // 0..7
        const int b    = q >> 2;
        const int i0   = (q & 3) * 64;
        nt64_body(g_Q + (b * 256 + i0) * 512 + n * 64, upos + n * 64,
                  g_K + (b * 256 + j0) * 512 + n * 64,
                  g_AC + ((b * 256 + i0) * 8 + n) * 256 + j0, 2048);
    }
}

// ---------------- attn: warp-autonomous, 2 m per CTA, T half-registered ----------------
// grid 256, 128 threads / 4 warps. Warp w: m = 2*bid + (w>>1), j in
// [(w&1)*128, +128), 32 groups of 4 j, per-warp cp.async double buffer, no
// block barriers in the mainloop. Lane holds T slices t=0,1 in registers
// (Treg, 64 regs) and reads t=2,3 from smem -> 32 LDS/group instead of 48.
// Butterfly leaves lane L with (n=L>>2, jj=L&3).
#define JG        4
#define NGRP      32
#define WBUF      (2 * JG * 512)            // 4096 floats per warp (16 KB)
#define OFF_T     (4 * WBUF)                // 16384
#define OFF_SS    (OFF_T + 2 * 4096)        // 24576
#define ATTN_SMEM ((OFF_SS + 16 * 260 + 16) * 4)   // 115008 B -> 2 CTAs/SM

__device__ __forceinline__ void attn_issue_group(float* mybuf, const float* rowsrc,
                                                 int lane, int g)
{
    float* dst = mybuf + (g & 1) * (JG * 512);
    const int r  = lane >> 3;
    const int c0 = lane & 7;
    const char* src = (const char*)(rowsrc + r * 512);
    uint32_t s = (uint32_t)__cvta_generic_to_shared(dst + r * 512);
    #pragma unroll
    for (int t = 0; t < 16; t++)
        cpasync16(s + (c0 + t * 8) * 16, src + (c0 + t * 8) * 16);
    cpasync_commit();
}

__global__ __launch_bounds__(128, 2)
void attn_kernel(const float* __restrict__ rpe,
                 const int* __restrict__ seq_len,
                 const int* __restrict__ lex_num)
{
    extern __shared__ __align__(16) float smem[];
    float* T_base = smem + OFF_T;
    float* ss     = smem + OFF_SS;     // 16 rows (2m x 8n) x 260
    __shared__ int s_limit;

    const int tid  = threadIdx.x;      // 0..127
    const int w    = tid >> 5;         // 0..3
    const int lane = tid & 31;
    const int m0   = blockIdx.x * 2;
    const int b    = blockIdx.x >> 7;
    const int wm   = w >> 1;           // which m this warp serves
    const int m    = m0 + wm;
    const int jw   = (w & 1) * 128;    // j offset

    const float* rpe_m = rpe + (size_t)m * 256 * 512;
    float* mybuf = smem + w * WBUF;
    float* T_s   = T_base + wm * 4096;

    attn_issue_group(mybuf, rpe_m + (size_t)(jw + 0 * JG) * 512, lane, 0);
    attn_issue_group(mybuf, rpe_m + (size_t)(jw + 1 * JG) * 512, lane, 1);

    // T for both m: 2048 float4, 128 threads x 16
    {
        const float4* src = (const float4*)(g_T + (size_t)m0 * 4096);
        float4* dst = (float4*)T_base;
        #pragma unroll
        for (int t = 0; t < 16; t++)
            dst[tid + 128 * t] = src[tid + 128 * t];
    }
    if (tid == 0) s_limit = seq_len[b] + lex_num[0];
    __syncthreads();

    // preload T slices t=0,1 into registers (16 LDS.128, once)
    ulonglong2 Treg[8][2];
    #pragma unroll
    for (int n = 0; n < 8; n++) {
        #pragma unroll
        for (int t = 0; t < 2; t++)
            Treg[n][t] = *(const ulonglong2*)(T_s + n * 512 + (lane + t * 32) * 4);
    }

    const int ssrow = wm * 8 + (lane >> 2);
    const int jj_l  = lane & 3;

    // ---- mainloop: 32 groups, no block barriers ----
    for (int g = 0; g < NGRP; g++) {
        // ledger: g<31 has one younger group in flight -> wait<1>; g==31 -> wait<0>
        if (g < NGRP - 1) cpasync_wait<1>(); else cpasync_wait<0>();
        __syncwarp();

        const float* rb = mybuf + (g & 1) * (JG * 512);
        unsigned long long acc[32] = {};
        #pragma unroll
        for (int t = 0; t < 4; t++) {
            const int f4 = (lane + t * 32) * 4;
            ulonglong2 rj[JG];
            #pragma unroll
            for (int jj = 0; jj < JG; jj++)
                rj[jj] = *(const ulonglong2*)(rb + jj * 512 + f4);
            #pragma unroll
            for (int n = 0; n < 8; n++) {
                ulonglong2 tv = (t < 2) ? Treg[n][t]
                                        : *(const ulonglong2*)(T_s + n * 512 + f4);
                #pragma unroll
                for (int jj = 0; jj < JG; jj++) {
                    acc[n * 4 + jj] = ffma2(rj[jj].x, tv.x, acc[n * 4 + jj]);
                    acc[n * 4 + jj] = ffma2(rj[jj].y, tv.y, acc[n * 4 + jj]);
                }
            }
        }

        if (g + 2 < NGRP)
            attn_issue_group(mybuf, rpe_m + (size_t)(jw + (g + 2) * JG) * 512, lane, g + 2);

        float v[32];
        #pragma unroll
        for (int i = 0; i < 32; i++) {
            float2 f2 = unpack2(acc[i]);
            v[i] = f2.x + f2.y;
        }
        #pragma unroll
        for (int s = 16; s >= 1; s >>= 1) {
            #pragma unroll
            for (int i = 0; i < 16; i++) {
                if (i < s) {
                    float send = (lane & s) ? v[i] : v[i + s];
                    float keep = (lane & s) ? v[i + s] : v[i];
                    v[i] = keep + __shfl_xor_sync(0xffffffffu, send, s);
                }
            }
        }
        // lane L: n = L>>2, jj = L&3
        ss[ssrow * 260 + jw + g * JG + jj_l] = v[0];
    }

    __syncthreads();

    // softmax: warp w handles rows w*4..w*4+3 (row = mloc*8 + n); fold AC/scale/mask
    const int limit = s_limit;
    #pragma unroll
    for (int k = 0; k < 4; k++) {
        const int r  = w * 4 + k;         // 0..15
        const int mm = m0 + (r >> 3);
        const int n  = r & 7;
        float vals[8];
        #pragma unroll
        for (int t = 0; t < 8; t++) {
            int j = lane + 32 * t;
            float raw = ss[r * 260 + j];
            float ac  = g_AC[((size_t)mm * 8 + n) * 256 + j];
            vals[t] = (j < limit) ? (raw + ac) * 0.125f : -1e15f;
        }
        float mx = vals[0];
        #pragma unroll
        for (int t = 1; t < 8; t++) mx = fmaxf(mx, vals[t]);
        #pragma unroll
        for (int o = 16; o; o >>= 1) mx = fmaxf(mx, __shfl_xor_sync(0xffffffffu, mx, o));
        float sum = 0.f;
        #pragma unroll
        for (int t = 0; t < 8; t++) { vals[t] = __expf(vals[t] - mx); sum += vals[t]; }
        #pragma unroll
        for (int o = 16; o; o >>= 1) sum += __shfl_xor_sync(0xffffffffu, sum, o);
        float inv = 1.f / sum;
        #pragma unroll
        for (int t = 0; t < 8; t++) ss[r * 260 + lane + 32 * t] = vals[t] * inv;
    }
    __syncthreads();

    // write P for both m: 1024 float4, 128 threads x 8
    {
        float4* P4 = (float4*)g_P + (size_t)m0 * 512;
        #pragma unroll
        for (int t = 0; t < 8; t++) {
            int f = tid + 128 * t;          // 0..1023
            int r = f >> 6;                 // row 0..15
            int c4 = f & 63;
            P4[f] = *(const float4*)&ss[r * 260 + c4 * 4];
        }
    }
}

// ---------------- ctx: CTX[m][n*64+d] = sum_j P[m][n][j] * V[b][j][n*64+d] ----------------
// 16-i tiles, grid (16,8,2)=256 blocks, 128 threads, 2x4 microtile, reg prefetch.
__global__ void ctx_kernel()
{
    __shared__ __align__(16) float Ps[64][18];   // [j][i], 16 i
    __shared__ __align__(16) float Vs[64][68];   // [j][d]

    const int tid = threadIdx.x;       // 0..127
    const int tx = tid & 15;           // d group (4 cols)
    const int ty = tid >> 4;           // 0..7 -> 2 i rows each
    const int i0 = blockIdx.x * 16;
    const int n  = blockIdx.y;
    const int b  = blockIdx.z;

    const int li = tid >> 3;           // P: i row 0..15
    const int jq = tid & 7;            // P: float4 cols jq, jq+8
    const int lj = tid >> 1;           // V: j row 0..63
    const int fl = tid & 1;            // V: float4 idx fl + 2q, q=0..7

    unsigned long long acc[2][2] = {};

    float4 pp[2], vv[8];
    {
        const float* Prow = &g_P[(((size_t)(b * 256 + i0 + li)) * 8 + n) * 256];
        pp[0] = *(const float4*)&Prow[(jq + 0) * 4];
        pp[1] = *(const float4*)&Prow[(jq + 8) * 4];
        const float* Vrow = &g_V[(size_t)(b * 256 + lj) * 512 + n * 64];
        #pragma unroll
        for (int q = 0; q < 8; q++)
            vv[q] = *(const float4*)&Vrow[(fl + q * 2) * 4];
    }

    for (int j0 = 0; j0 < 256; j0 += 64) {
        #pragma unroll
        for (int q = 0; q < 2; q++) {
            int jf = jq + q * 8;
            Ps[jf * 4 + 0][li] = pp[q].x;
            Ps[jf * 4 + 1][li] = pp[q].y;
            Ps[jf * 4 + 2][li] = pp[q].z;
            Ps[jf * 4 + 3][li] = pp[q].w;
        }
        #pragma unroll
        for (int q = 0; q < 8; q++)
            *(float4*)&Vs[lj][(fl + q * 2) * 4] = vv[q];
        __syncthreads();

        if (j0 + 64 < 256) {
            const float* Prow = &g_P[(((size_t)(b * 256 + i0 + li)) * 8 + n) * 256 + j0 + 64];
            pp[0] = *(const float4*)&Prow[(jq + 0) * 4];
            pp[1] = *(const float4*)&Prow[(jq + 8) * 4];
            const float* Vrow = &g_V[(size_t)(b * 256 + j0 + 64 + lj) * 512 + n * 64];
            #pragma unroll
            for (int q = 0; q < 8; q++)
                vv[q] = *(const float4*)&Vrow[(fl + q * 2) * 4];
        }

        #pragma unroll 16
        for (int j = 0; j < 64; j++) {
            float2 av = *(const float2*)&Ps[j][ty * 2];
            ulonglong2 bp = *(const ulonglong2*)&Vs[j][tx * 4];
            unsigned long long s0 = splat2(av.x);
            unsigned long long s1 = splat2(av.y);
            acc[0][0] = ffma2(s0, bp.x, acc[0][0]); acc[0][1] = ffma2(s0, bp.y, acc[0][1]);
            acc[1][0] = ffma2(s1, bp.x, acc[1][0]); acc[1][1] = ffma2(s1, bp.y, acc[1][1]);
        }
        __syncthreads();
    }

    #pragma unroll
    for (int r = 0; r < 2; r++) {
        float2 p0 = unpack2(acc[r][0]);
        float2 p1 = unpack2(acc[r][1]);
        float4 o; o.x = p0.x; o.y = p0.y; o.z = p1.x; o.w = p1.y;
        *(float4*)&g_CTX[(size_t)(b * 256 + i0 + ty * 2 + r) * 512 + n * 64 + tx * 4] = o;
    }
}

// ---------------- launch ----------------
extern "C" void kernel_launch(void* const* d_in, const int* in_sizes, int n_in,
                              void* d_out, int out_size)
{
    const float* key     = (const float*)d_in[0];
    const float* query   = (const float*)d_in[1];
    const float* value   = (const float*)d_in[2];
    const int*   seq_len = (const int*)  d_in[3];
    const int*   lex_num = (const int*)  d_in[4];
    const float* rpe     = (const float*)d_in[7];
    const float* Wk      = (const float*)d_in[8];
    const float* bk      = (const float*)d_in[9];
    const float* Wq      = (const float*)d_in[10];
    const float* bq      = (const float*)d_in[11];
    const float* Wv      = (const float*)d_in[12];
    const float* bv      = (const float*)d_in[13];
    const float* Wr      = (const float*)d_in[14];
    const float* upos    = (const float*)d_in[16];
    const float* vpos    = (const float*)d_in[17];
    const float* Wf      = (const float*)d_in[18];
    const float* bf      = (const float*)d_in[19];
    float* out = (float*)d_out;

    static bool attr_set = false;
    if (!attr_set) {
        cudaFuncSetAttribute(attn_kernel,
                             cudaFuncAttributeMaxDynamicSharedMemorySize, ATTN_SMEM);
        attr_set = true;
    }

    proj_kernel <<<dim3(8, 16, 3), 128>>>(key, query, value, Wk, bk, Wq, bq, Wv, bv);
    tac_kernel  <<<dim3(768), 256>>>(Wr, vpos, upos);
    attn_kernel <<<dim3(BB * LL / 2), 128, ATTN_SMEM>>>(rpe, seq_len, lex_num);
    ctx_kernel  <<<dim3(16, 8, 2), 256 / 2>>>();
    final_kernel<<<dim3(8, 16), 128>>>(Wf, bf, out);
}

// round 13
// speedup vs baseline: 1.0210x; 1.0210x over previous
#include <cuda_runtime.h>
#include <cstdint>

#define BB 2
#define LL 256
#define HH 512
#define NHH 8
#define DHH 64

// ---------------- scratch (device globals; no allocation) ----------------
__device__ __align__(16) float g_K[BB*LL*HH];
__device__ __align__(16) float g_Q[BB*LL*HH];
__device__ __align__(16) float g_V[BB*LL*HH];
__device__ __align__(16) float g_T[BB*LL*NHH*HH];    // [m][n][h]  8 MB
__device__ __align__(16) float g_AC[BB*LL*NHH*LL];   // [m][n][j]  4 MB
__device__ __align__(16) float g_P[BB*LL*NHH*LL];    // [m][n][j]  4 MB
__device__ __align__(16) float g_CTX[BB*LL*HH];

// ---------------- f32x2 helpers ----------------
__device__ __forceinline__ unsigned long long ffma2(unsigned long long a,
                                                    unsigned long long b,
                                                    unsigned long long c) {
    unsigned long long d;
    asm("fma.rn.f32x2 %0, %1, %2, %3;" : "=l"(d) : "l"(a), "l"(b), "l"(c));
    return d;
}
__device__ __forceinline__ unsigned long long splat2(float a) {
    unsigned long long r;
    asm("mov.b64 %0, {%1, %1};" : "=l"(r) : "f"(a));
    return r;
}
__device__ __forceinline__ float2 unpack2(unsigned long long v) {
    float2 f;
    asm("mov.b64 {%0, %1}, %2;" : "=f"(f.x), "=f"(f.y) : "l"(v));
    return f;
}
__device__ __forceinline__ void cpasync16(uint32_t s, const void* g) {
    asm volatile("cp.async.cg.shared.global [%0], [%1], 16;\n" :: "r"(s), "l"(g));
}
__device__ __forceinline__ void cpasync_commit() {
    asm volatile("cp.async.commit_group;\n" ::: "memory");
}
template <int N>
__device__ __forceinline__ void cpasync_wait() {
    asm volatile("cp.async.wait_group %0;\n" :: "n"(N) : "memory");
}

// ---------------- 32x64-tile GEMM, 128 threads, 4x4 microtile ----------------
__device__ __forceinline__ void gemm32x64_body(const float* __restrict__ A,
                                               const float* __restrict__ W,
                                               const float* __restrict__ bias,
                                               float* __restrict__ C)
{
    __shared__ __align__(16) float As[32][36];   // [k][m]
    __shared__ __align__(16) float Bs[32][68];   // [k][n]

    const int tid = threadIdx.x;        // 0..127
    const int tx  = tid & 15;
    const int ty  = tid >> 4;
    const int row0 = blockIdx.y * 32;
    const int col0 = blockIdx.x * 64;

    const int lm = tid >> 2;            // A row 0..31
    const int lk = (tid & 3) * 8;       // A k offset
    const int brr = tid >> 4;           // B base row 0..7
    const int bc  = (tid & 15) * 4;     // B col offset

    float4 a0 = *(const float4*)&A[(row0 + lm) * 512 + lk];
    float4 a1 = *(const float4*)&A[(row0 + lm) * 512 + lk + 4];
    float4 b0 = *(const float4*)&W[(brr +  0) * 512 + col0 + bc];
    float4 b1 = *(const float4*)&W[(brr +  8) * 512 + col0 + bc];
    float4 b2 = *(const float4*)&W[(brr + 16) * 512 + col0 + bc];
    float4 b3 = *(const float4*)&W[(brr + 24) * 512 + col0 + bc];

    unsigned long long acc[4][2] = {};

    for (int kt = 0; kt < 512; kt += 32) {
        As[lk + 0][lm] = a0.x; As[lk + 1][lm] = a0.y;
        As[lk + 2][lm] = a0.z; As[lk + 3][lm] = a0.w;
        As[lk + 4][lm] = a1.x; As[lk + 5][lm] = a1.y;
        As[lk + 6][lm] = a1.z; As[lk + 7][lm] = a1.w;
        *(float4*)&Bs[brr +  0][bc] = b0;
        *(float4*)&Bs[brr +  8][bc] = b1;
        *(float4*)&Bs[brr + 16][bc] = b2;
        *(float4*)&Bs[brr + 24][bc] = b3;
        __syncthreads();

        if (kt + 32 < 512) {
            a0 = *(const float4*)&A[(row0 + lm) * 512 + kt + 32 + lk];
            a1 = *(const float4*)&A[(row0 + lm) * 512 + kt + 32 + lk + 4];
            b0 = *(const float4*)&W[(kt + 32 + brr +  0) * 512 + col0 + bc];
            b1 = *(const float4*)&W[(kt + 32 + brr +  8) * 512 + col0 + bc];
            b2 = *(const float4*)&W[(kt + 32 + brr + 16) * 512 + col0 + bc];
            b3 = *(const float4*)&W[(kt + 32 + brr + 24) * 512 + col0 + bc];
        }

        #pragma unroll
        for (int kk = 0; kk < 32; kk++) {
            float4 av = *(const float4*)&As[kk][ty * 4];
            ulonglong2 bp = *(const ulonglong2*)&Bs[kk][tx * 4];
            unsigned long long s0 = splat2(av.x);
            unsigned long long s1 = splat2(av.y);
            unsigned long long s2 = splat2(av.z);
            unsigned long long s3 = splat2(av.w);
            acc[0][0] = ffma2(s0, bp.x, acc[0][0]); acc[0][1] = ffma2(s0, bp.y, acc[0][1]);
            acc[1][0] = ffma2(s1, bp.x, acc[1][0]); acc[1][1] = ffma2(s1, bp.y, acc[1][1]);
            acc[2][0] = ffma2(s2, bp.x, acc[2][0]); acc[2][1] = ffma2(s2, bp.y, acc[2][1]);
            acc[3][0] = ffma2(s3, bp.x, acc[3][0]); acc[3][1] = ffma2(s3, bp.y, acc[3][1]);
        }
        __syncthreads();
    }

    float4 bb = *(const float4*)&bias[col0 + tx * 4];
    #pragma unroll
    for (int r = 0; r < 4; r++) {
        float2 p0 = unpack2(acc[r][0]);
        float2 p1 = unpack2(acc[r][1]);
        float4 o;
        o.x = p0.x + bb.x; o.y = p0.y + bb.y;
        o.z = p1.x + bb.z; o.w = p1.y + bb.w;
        *(float4*)&C[(row0 + ty * 4 + r) * 512 + col0 + tx * 4] = o;
    }
}

__global__ void proj_kernel(const float* __restrict__ key,
                            const float* __restrict__ query,
                            const float* __restrict__ value,
                            const float* __restrict__ Wk, const float* __restrict__ bk,
                            const float* __restrict__ Wq, const float* __restrict__ bq,
                            const float* __restrict__ Wv, const float* __restrict__ bv)
{
    const float *A, *W, *bias;
    float* C;
    if (blockIdx.z == 0)      { A = key;   W = Wk; bias = bk; C = g_K; }
    else if (blockIdx.z == 1) { A = query; W = Wq; bias = bq; C = g_Q; }
    else                      { A = value; W = Wv; bias = bv; C = g_V; }
    gemm32x64_body(A, W, bias, C);
}

__global__ void final_kernel(const float* __restrict__ Wf,
                             const float* __restrict__ bf,
                             float* __restrict__ out)
{
    gemm32x64_body(g_CTX, Wf, bf, out);
}

// ---------------- K=64 A@B^T body (tilde + AC), register-prefetched ----------------
__device__ __forceinline__ void nt64_body(const float* __restrict__ Arow0,
                                          const float* __restrict__ avec,
                                          const float* __restrict__ Brow0,
                                          float* __restrict__ Cbase, int ldc)
{
    __shared__ __align__(16) float As[16][68];
    __shared__ __align__(16) float Bs[16][68];

    const int tid = threadIdx.x;
    const int tx = tid & 15, ty = tid >> 4;
    const int lm = tid >> 2;
    const int lk = (tid & 3) * 4;

    unsigned long long acc[4][2] = {};

    float4 a_n = *(const float4*)&Arow0[lm * 512 + lk];
    float4 b_n = *(const float4*)&Brow0[lm * 512 + lk];

    for (int kt = 0; kt < 64; kt += 16) {
        float4 vb = *(const float4*)&avec[kt + lk];
        As[lk + 0][lm] = a_n.x + vb.x; As[lk + 1][lm] = a_n.y + vb.y;
        As[lk + 2][lm] = a_n.z + vb.z; As[lk + 3][lm] = a_n.w + vb.w;
        Bs[lk + 0][lm] = b_n.x; Bs[lk + 1][lm] = b_n.y;
        Bs[lk + 2][lm] = b_n.z; Bs[lk + 3][lm] = b_n.w;
        __syncthreads();

        if (kt + 16 < 64) {
            a_n = *(const float4*)&Arow0[lm * 512 + kt + 16 + lk];
            b_n = *(const float4*)&Brow0[lm * 512 + kt + 16 + lk];
        }

        #pragma unroll
        for (int kk = 0; kk < 16; kk++) {
            float4 av = *(const float4*)&As[kk][ty * 4];
            ulonglong2 bp = *(const ulonglong2*)&Bs[kk][tx * 4];
            unsigned long long s0 = splat2(av.x);
            unsigned long long s1 = splat2(av.y);
            unsigned long long s2 = splat2(av.z);
            unsigned long long s3 = splat2(av.w);
            acc[0][0] = ffma2(s0, bp.x, acc[0][0]); acc[0][1] = ffma2(s0, bp.y, acc[0][1]);
            acc[1][0] = ffma2(s1, bp.x, acc[1][0]); acc[1][1] = ffma2(s1, bp.y, acc[1][1]);
            acc[2][0] = ffma2(s2, bp.x, acc[2][0]); acc[2][1] = ffma2(s2, bp.y, acc[2][1]);
            acc[3][0] = ffma2(s3, bp.x, acc[3][0]); acc[3][1] = ffma2(s3, bp.y, acc[3][1]);
        }
        __syncthreads();
    }

    #pragma unroll
    for (int r = 0; r < 4; r++) {
        float2 p0 = unpack2(acc[r][0]);
        float2 p1 = unpack2(acc[r][1]);
        float4 o; o.x = p0.x; o.y = p0.y; o.z = p1.x; o.w = p1.y;
        *(float4*)&Cbase[(ty * 4 + r) * ldc + tx * 4] = o;
    }
}

// tilde (bid<512): T[m][n][h] = sum_d (Q[m][n*64+d]+vpos[n*64+d]) * Wr[h][n*64+d]
// ac (bid>=512):   AC[m][n][j] = sum_d (Q[m][n*64+d]+upos[n*64+d]) * K[b][j][n*64+d]
__global__ void tac_kernel(const float* __restrict__ Wr,
                           const float* __restrict__ vpos,
                           const float* __restrict__ upos)
{
    const int bid = blockIdx.x;
    if (bid < 512) {
        const int n    = bid >> 6;
        const int rest = bid & 63;
        const int h0   = (rest & 7) * 64;
        const int m0   = (rest >> 3) * 64;
        nt64_body(g_Q + m0 * 512 + n * 64, vpos + n * 64,
                  Wr + h0 * 512 + n * 64,
                  g_T + (m0 * 8 + n) * 512 + h0, 4096);
    } else {
        const int r    = bid - 512;
        const int n    = r >> 5;
        const int rest = r & 31;
        const int j0   = (rest & 3) * 64;
        const int q    = rest >> 2;          // 0..7
        const int b    = q >> 2;
        const int i0   = (q & 3) * 64;
        nt64_body(g_Q + (b * 256 + i0) * 512 + n * 64, upos + n * 64,
                  g_K + (b * 256 + j0) * 512 + n * 64,
                  g_AC + ((b * 256 + i0) * 8 + n) * 256 + j0, 2048);
    }
}

// ---------------- attn: warp-autonomous scores + softmax -> P (R10 best) ----------------
// 128 threads / 4 warps per CTA, 2 CTAs/SM. Warp w owns j in [w*64, w*64+64),
// 16 groups of 4 j, per-warp cp.async double buffer, no block barriers in the
// mainloop. Lane covers h float4 indices {lane + 32t, t=0..3} for all 8 n and
// 4 j; merged butterfly leaves lane L with score (n=L>>2, jj=L&3).
#define JG        4
#define NGRP      16
#define WBUF      (2 * JG * 512)            // 4096 floats per warp (16 KB)
#define OFF_T     (4 * WBUF)                // 16384
#define OFF_SS    (OFF_T + 4096)            // 20480
#define ATTN_SMEM ((OFF_SS + 2080 + 16) * 4)  // 90304 bytes -> 2 CTAs/SM

__device__ __forceinline__ void attn_issue_group(float* mybuf, const float* rowsrc,
                                                 int lane, int g)
{
    float* dst = mybuf + (g & 1) * (JG * 512);
    const int r  = lane >> 3;
    const int c0 = lane & 7;
    const char* src = (const char*)(rowsrc + r * 512);
    uint32_t s = (uint32_t)__cvta_generic_to_shared(dst + r * 512);
    #pragma unroll
    for (int t = 0; t < 16; t++)
        cpasync16(s + (c0 + t * 8) * 16, src + (c0 + t * 8) * 16);
    cpasync_commit();
}

__global__ __launch_bounds__(128, 2)
void attn_kernel(const float* __restrict__ rpe,
                 const int* __restrict__ seq_len,
                 const int* __restrict__ lex_num)
{
    extern __shared__ __align__(16) float smem[];
    float* T_s = smem + OFF_T;
    float* ss  = smem + OFF_SS;
    __shared__ int s_limit;

    const int tid  = threadIdx.x;     // 0..127
    const int m    = blockIdx.x;
    const int b    = m >> 8;
    const int w    = tid >> 5;        // 0..3
    const int lane = tid & 31;
    const int jw   = w * 64;

    const float* rpe_m = rpe + (size_t)m * 256 * 512;
    float* mybuf = smem + w * WBUF;

    attn_issue_group(mybuf, rpe_m + (size_t)(jw + 0 * JG) * 512, lane, 0);
    attn_issue_group(mybuf, rpe_m + (size_t)(jw + 1 * JG) * 512, lane, 1);

    // T rows for this m: 1024 float4, 128 threads x 8
    {
        const float4* src = (const float4*)(g_T + (size_t)m * 4096);
        float4* dst = (float4*)T_s;
        #pragma unroll
        for (int t = 0; t < 8; t++)
            dst[tid + 128 * t] = src[tid + 128 * t];
    }
    if (tid == 0) s_limit = seq_len[b] + lex_num[0];
    __syncthreads();

    // ---- mainloop: 16 groups, no block barriers ----
    for (int g = 0; g < NGRP; g++) {
        // ledger: g<15 has one younger group in flight -> wait<1>; g==15 -> wait<0>
        if (g < NGRP - 1) cpasync_wait<1>(); else cpasync_wait<0>();
        __syncwarp();

        const float* rb = mybuf + (g & 1) * (JG * 512);
        unsigned long long acc[32] = {};
        #pragma unroll
        for (int t = 0; t < 4; t++) {
            const int f4 = (lane + t * 32) * 4;
            ulonglong2 rj[JG];
            #pragma unroll
            for (int jj = 0; jj < JG; jj++)
                rj[jj] = *(const ulonglong2*)(rb + jj * 512 + f4);
            #pragma unroll
            for (int n = 0; n < 8; n++) {
                ulonglong2 tv = *(const ulonglong2*)(T_s + n * 512 + f4);
                #pragma unroll
                for (int jj = 0; jj < JG; jj++) {
                    acc[n * 4 + jj] = ffma2(rj[jj].x, tv.x, acc[n * 4 + jj]);
                    acc[n * 4 + jj] = ffma2(rj[jj].y, tv.y, acc[n * 4 + jj]);
                }
            }
        }

        if (g + 2 < NGRP)
            attn_issue_group(mybuf, rpe_m + (size_t)(jw + (g + 2) * JG) * 512, lane, g + 2);

        float v[32];
        #pragma unroll
        for (int i = 0; i < 32; i++) {
            float2 f2 = unpack2(acc[i]);
            v[i] = f2.x + f2.y;
        }
        #pragma unroll
        for (int s = 16; s >= 1; s >>= 1) {
            #pragma unroll
            for (int i = 0; i < 16; i++) {
                if (i < s) {
                    float send = (lane & s) ? v[i] : v[i + s];
                    float keep = (lane & s) ? v[i + s] : v[i];
                    v[i] = keep + __shfl_xor_sync(0xffffffffu, send, s);
                }
            }
        }
        // lane L: n = L>>2, jj = L&3
        ss[(lane >> 2) * 260 + jw + g * JG + (lane & 3)] = v[0];
    }

    __syncthreads();

    // softmax: warp w handles heads w and w+4; fold in AC, scale, mask
    const int limit = s_limit;
    #pragma unroll
    for (int hh = 0; hh < 2; hh++) {
        const int n = w + hh * 4;
        float vals[8];
        #pragma unroll
        for (int t = 0; t < 8; t++) {
            int j = lane + 32 * t;
            float raw = ss[n * 260 + j];
            float ac  = g_AC[((size_t)m * 8 + n) * 256 + j];
            vals[t] = (j < limit) ? (raw + ac) * 0.125f : -1e15f;
        }
        float mx = vals[0];
        #pragma unroll
        for (int t = 1; t < 8; t++) mx = fmaxf(mx, vals[t]);
        #pragma unroll
        for (int o = 16; o; o >>= 1) mx = fmaxf(mx, __shfl_xor_sync(0xffffffffu, mx, o));
        float sum = 0.f;
        #pragma unroll
        for (int t = 0; t < 8; t++) { vals[t] = __expf(vals[t] - mx); sum += vals[t]; }
        #pragma unroll
        for (int o = 16; o; o >>= 1) sum += __shfl_xor_sync(0xffffffffu, sum, o);
        float inv = 1.f / sum;
        #pragma unroll
        for (int t = 0; t < 8; t++) ss[n * 260 + lane + 32 * t] = vals[t] * inv;
    }
    __syncthreads();

    // write P: 512 float4, 128 threads x 4
    {
        float4* P4 = (float4*)g_P + (size_t)m * 512;
        #pragma unroll
        for (int t = 0; t < 4; t++) {
            int f = tid + 128 * t;
            int n = f >> 6;
            int c4 = f & 63;
            P4[f] = *(const float4*)&ss[n * 260 + c4 * 4];
        }
    }
}

// ---------------- ctx: CTX[m][n*64+d] = sum_j P[m][n][j] * V[b][j][n*64+d] ----------------
// R11 best: 32-i tiles, grid (8,8,2), 256 threads, 2x4 microtile, reg prefetch.
__global__ void ctx_kernel()
{
    __shared__ __align__(16) float Ps[64][34];
    __shared__ __align__(16) float Vs[64][68];

    const int tid = threadIdx.x;
    const int tx = tid & 15, ty = tid >> 4;
    const int i0 = blockIdx.x * 32;
    const int n  = blockIdx.y;
    const int b  = blockIdx.z;

    const int li = tid >> 3;            // P: i row 0..31
    const int jq = tid & 7;             // P: 2 float4 per thread (jq, jq+8)
    const int lj = tid >> 2;            // V: j row 0..63
    const int fl = tid & 3;             // V: 4 float4 per thread

    unsigned long long acc[2][2] = {};

    float4 pp[2], vv[4];
    {
        const float* Prow = &g_P[(((size_t)(b * 256 + i0 + li)) * 8 + n) * 256];
        pp[0] = *(const float4*)&Prow[(jq + 0) * 4];
        pp[1] = *(const float4*)&Prow[(jq + 8) * 4];
        const float* Vrow = &g_V[(size_t)(b * 256 + lj) * 512 + n * 64];
        #pragma unroll
        for (int q = 0; q < 4; q++)
            vv[q] = *(const float4*)&Vrow[(fl + q * 4) * 4];
    }

    for (int j0 = 0; j0 < 256; j0 += 64) {
        #pragma unroll
        for (int q = 0; q < 2; q++) {
            int jf = jq + q * 8;
            Ps[jf * 4 + 0][li] = pp[q].x;
            Ps[jf * 4 + 1][li] = pp[q].y;
            Ps[jf * 4 + 2][li] = pp[q].z;
            Ps[jf * 4 + 3][li] = pp[q].w;
        }
        #pragma unroll
        for (int q = 0; q < 4; q++)
            *(float4*)&Vs[lj][(fl + q * 4) * 4] = vv[q];
        __syncthreads();

        if (j0 + 64 < 256) {
            const float* Prow = &g_P[(((size_t)(b * 256 + i0 + li)) * 8 + n) * 256 + j0 + 64];
            pp[0] = *(const float4*)&Prow[(jq + 0) * 4];
            pp[1] = *(const float4*)&Prow[(jq + 8) * 4];
            const float* Vrow = &g_V[(size_t)(b * 256 + j0 + 64 + lj) * 512 + n * 64];
            #pragma unroll
            for (int q = 0; q < 4; q++)
                vv[q] = *(const float4*)&Vrow[(fl + q * 4) * 4];
        }

        #pragma unroll 16
        for (int j = 0; j < 64; j++) {
            float2 av = *(const float2*)&Ps[j][ty * 2];
            ulonglong2 bp = *(const ulonglong2*)&Vs[j][tx * 4];
            unsigned long long s0 = splat2(av.x);
            unsigned long long s1 = splat2(av.y);
            acc[0][0] = ffma2(s0, bp.x, acc[0][0]); acc[0][1] = ffma2(s0, bp.y, acc[0][1]);
            acc[1][0] = ffma2(s1, bp.x, acc[1][0]); acc[1][1] = ffma2(s1, bp.y, acc[1][1]);
        }
        __syncthreads();
    }

    #pragma unroll
    for (int r = 0; r < 2; r++) {
        float2 p0 = unpack2(acc[r][0]);
        float2 p1 = unpack2(acc[r][1]);
        float4 o; o.x = p0.x; o.y = p0.y; o.z = p1.x; o.w = p1.y;
        *(float4*)&g_CTX[(size_t)(b * 256 + i0 + ty * 2 + r) * 512 + n * 64 + tx * 4] = o;
    }
}

// ---------------- launch ----------------
extern "C" void kernel_launch(void* const* d_in, const int* in_sizes, int n_in,
                              void* d_out, int out_size)
{
    const float* key     = (const float*)d_in[0];
    const float* query   = (const float*)d_in[1];
    const float* value   = (const float*)d_in[2];
    const int*   seq_len = (const int*)  d_in[3];
    const int*   lex_num = (const int*)  d_in[4];
    const float* rpe     = (const float*)d_in[7];
    const float* Wk      = (const float*)d_in[8];
    const float* bk      = (const float*)d_in[9];
    const float* Wq      = (const float*)d_in[10];
    const float* bq      = (const float*)d_in[11];
    const float* Wv      = (const float*)d_in[12];
    const float* bv      = (const float*)d_in[13];
    const float* Wr      = (const float*)d_in[14];
    const float* upos    = (const float*)d_in[16];
    const float* vpos    = (const float*)d_in[17];
    const float* Wf      = (const float*)d_in[18];
    const float* bf      = (const float*)d_in[19];
    float* out = (float*)d_out;

    static bool attr_set = false;
    if (!attr_set) {
        cudaFuncSetAttribute(attn_kernel,
                             cudaFuncAttributeMaxDynamicSharedMemorySize, ATTN_SMEM);
        attr_set = true;
    }

    proj_kernel <<<dim3(8, 16, 3), 128>>>(key, query, value, Wk, bk, Wq, bq, Wv, bv);
    tac_kernel  <<<dim3(768), 256>>>(Wr, vpos, upos);
    attn_kernel <<<dim3(BB * LL), 128, ATTN_SMEM>>>(rpe, seq_len, lex_num);
    ctx_kernel  <<<dim3(8, 8, 2), 256>>>();
    final_kernel<<<dim3(8, 16), 128>>>(Wf, bf, out);
}

// round 14
// speedup vs baseline: 1.0313x; 1.0101x over previous
#include <cuda_runtime.h>
#include <cstdint>

#define BB 2
#define LL 256
#define HH 512
#define NHH 8
#define DHH 64

// ---------------- scratch (device globals; no allocation) ----------------
__device__ __align__(16) float g_K[BB*LL*HH];
__device__ __align__(16) float g_Q[BB*LL*HH];
__device__ __align__(16) float g_V[BB*LL*HH];
__device__ __align__(16) float g_T[BB*LL*NHH*HH];    // [m][n][h]  8 MB
__device__ __align__(16) float g_AC[BB*LL*NHH*LL];   // [m][n][j]  4 MB
__device__ __align__(16) float g_P[BB*LL*NHH*LL];    // [m][n][j]  4 MB
__device__ __align__(16) float g_CTX[BB*LL*HH];

// ---------------- f32x2 helpers ----------------
__device__ __forceinline__ unsigned long long ffma2(unsigned long long a,
                                                    unsigned long long b,
                                                    unsigned long long c) {
    unsigned long long d;
    asm("fma.rn.f32x2 %0, %1, %2, %3;" : "=l"(d) : "l"(a), "l"(b), "l"(c));
    return d;
}
__device__ __forceinline__ unsigned long long splat2(float a) {
    unsigned long long r;
    asm("mov.b64 %0, {%1, %1};" : "=l"(r) : "f"(a));
    return r;
}
__device__ __forceinline__ float2 unpack2(unsigned long long v) {
    float2 f;
    asm("mov.b64 {%0, %1}, %2;" : "=f"(f.x), "=f"(f.y) : "l"(v));
    return f;
}
__device__ __forceinline__ void cpasync16(uint32_t s, const void* g) {
    asm volatile("cp.async.cg.shared.global [%0], [%1], 16;\n" :: "r"(s), "l"(g));
}
__device__ __forceinline__ void cpasync_commit() {
    asm volatile("cp.async.commit_group;\n" ::: "memory");
}
template <int N>
__device__ __forceinline__ void cpasync_wait() {
    asm volatile("cp.async.wait_group %0;\n" :: "n"(N) : "memory");
}

// ---------------- 32x64-tile GEMM, 128 threads, 4x4 microtile ----------------
__device__ __forceinline__ void gemm32x64_body(const float* __restrict__ A,
                                               const float* __restrict__ W,
                                               const float* __restrict__ bias,
                                               float* __restrict__ C)
{
    __shared__ __align__(16) float As[32][36];   // [k][m]
    __shared__ __align__(16) float Bs[32][68];   // [k][n]

    const int tid = threadIdx.x;        // 0..127
    const int tx  = tid & 15;
    const int ty  = tid >> 4;
    const int row0 = blockIdx.y * 32;
    const int col0 = blockIdx.x * 64;

    const int lm = tid >> 2;            // A row 0..31
    const int lk = (tid & 3) * 8;       // A k offset
    const int brr = tid >> 4;           // B base row 0..7
    const int bc  = (tid & 15) * 4;     // B col offset

    float4 a0 = *(const float4*)&A[(row0 + lm) * 512 + lk];
    float4 a1 = *(const float4*)&A[(row0 + lm) * 512 + lk + 4];
    float4 b0 = *(const float4*)&W[(brr +  0) * 512 + col0 + bc];
    float4 b1 = *(const float4*)&W[(brr +  8) * 512 + col0 + bc];
    float4 b2 = *(const float4*)&W[(brr + 16) * 512 + col0 + bc];
    float4 b3 = *(const float4*)&W[(brr + 24) * 512 + col0 + bc];

    unsigned long long acc[4][2] = {};

    for (int kt = 0; kt < 512; kt += 32) {
        As[lk + 0][lm] = a0.x; As[lk + 1][lm] = a0.y;
        As[lk + 2][lm] = a0.z; As[lk + 3][lm] = a0.w;
        As[lk + 4][lm] = a1.x; As[lk + 5][lm] = a1.y;
        As[lk + 6][lm] = a1.z; As[lk + 7][lm] = a1.w;
        *(float4*)&Bs[brr +  0][bc] = b0;
        *(float4*)&Bs[brr +  8][bc] = b1;
        *(float4*)&Bs[brr + 16][bc] = b2;
        *(float4*)&Bs[brr + 24][bc] = b3;
        __syncthreads();

        if (kt + 32 < 512) {
            a0 = *(const float4*)&A[(row0 + lm) * 512 + kt + 32 + lk];
            a1 = *(const float4*)&A[(row0 + lm) * 512 + kt + 32 + lk + 4];
            b0 = *(const float4*)&W[(kt + 32 + brr +  0) * 512 + col0 + bc];
            b1 = *(const float4*)&W[(kt + 32 + brr +  8) * 512 + col0 + bc];
            b2 = *(const float4*)&W[(kt + 32 + brr + 16) * 512 + col0 + bc];
            b3 = *(const float4*)&W[(kt + 32 + brr + 24) * 512 + col0 + bc];
        }

        #pragma unroll
        for (int kk = 0; kk < 32; kk++) {
            float4 av = *(const float4*)&As[kk][ty * 4];
            ulonglong2 bp = *(const ulonglong2*)&Bs[kk][tx * 4];
            unsigned long long s0 = splat2(av.x);
            unsigned long long s1 = splat2(av.y);
            unsigned long long s2 = splat2(av.z);
            unsigned long long s3 = splat2(av.w);
            acc[0][0] = ffma2(s0, bp.x, acc[0][0]); acc[0][1] = ffma2(s0, bp.y, acc[0][1]);
            acc[1][0] = ffma2(s1, bp.x, acc[1][0]); acc[1][1] = ffma2(s1, bp.y, acc[1][1]);
            acc[2][0] = ffma2(s2, bp.x, acc[2][0]); acc[2][1] = ffma2(s2, bp.y, acc[2][1]);
            acc[3][0] = ffma2(s3, bp.x, acc[3][0]); acc[3][1] = ffma2(s3, bp.y, acc[3][1]);
        }
        __syncthreads();
    }

    float4 bb = *(const float4*)&bias[col0 + tx * 4];
    #pragma unroll
    for (int r = 0; r < 4; r++) {
        float2 p0 = unpack2(acc[r][0]);
        float2 p1 = unpack2(acc[r][1]);
        float4 o;
        o.x = p0.x + bb.x; o.y = p0.y + bb.y;
        o.z = p1.x + bb.z; o.w = p1.y + bb.w;
        *(float4*)&C[(row0 + ty * 4 + r) * 512 + col0 + tx * 4] = o;
    }
}

__global__ void proj_kernel(const float* __restrict__ key,
                            const float* __restrict__ query,
                            const float* __restrict__ value,
                            const float* __restrict__ Wk, const float* __restrict__ bk,
                            const float* __restrict__ Wq, const float* __restrict__ bq,
                            const float* __restrict__ Wv, const float* __restrict__ bv)
{
    const float *A, *W, *bias;
    float* C;
    if (blockIdx.z == 0)      { A = key;   W = Wk; bias = bk; C = g_K; }
    else if (blockIdx.z == 1) { A = query; W = Wq; bias = bq; C = g_Q; }
    else                      { A = value; W = Wv; bias = bv; C = g_V; }
    gemm32x64_body(A, W, bias, C);
}

__global__ void final_kernel(const float* __restrict__ Wf,
                             const float* __restrict__ bf,
                             float* __restrict__ out)
{
    gemm32x64_body(g_CTX, Wf, bf, out);
}

// ---------------- K=64 A@B^T body (tilde + AC), register-prefetched ----------------
__device__ __forceinline__ void nt64_body(const float* __restrict__ Arow0,
                                          const float* __restrict__ avec,
                                          const float* __restrict__ Brow0,
                                          float* __restrict__ Cbase, int ldc)
{
    __shared__ __align__(16) float As[16][68];
    __shared__ __align__(16) float Bs[16][68];

    const int tid = threadIdx.x;
    const int tx = tid & 15, ty = tid >> 4;
    const int lm = tid >> 2;
    const int lk = (tid & 3) * 4;

    unsigned long long acc[4][2] = {};

    float4 a_n = *(const float4*)&Arow0[lm * 512 + lk];
    float4 b_n = *(const float4*)&Brow0[lm * 512 + lk];

    for (int kt = 0; kt < 64; kt += 16) {
        float4 vb = *(const float4*)&avec[kt + lk];
        As[lk + 0][lm] = a_n.x + vb.x; As[lk + 1][lm] = a_n.y + vb.y;
        As[lk + 2][lm] = a_n.z + vb.z; As[lk + 3][lm] = a_n.w + vb.w;
        Bs[lk + 0][lm] = b_n.x; Bs[lk + 1][lm] = b_n.y;
        Bs[lk + 2][lm] = b_n.z; Bs[lk + 3][lm] = b_n.w;
        __syncthreads();

        if (kt + 16 < 64) {
            a_n = *(const float4*)&Arow0[lm * 512 + kt + 16 + lk];
            b_n = *(const float4*)&Brow0[lm * 512 + kt + 16 + lk];
        }

        #pragma unroll
        for (int kk = 0; kk < 16; kk++) {
            float4 av = *(const float4*)&As[kk][ty * 4];
            ulonglong2 bp = *(const ulonglong2*)&Bs[kk][tx * 4];
            unsigned long long s0 = splat2(av.x);
            unsigned long long s1 = splat2(av.y);
            unsigned long long s2 = splat2(av.z);
            unsigned long long s3 = splat2(av.w);
            acc[0][0] = ffma2(s0, bp.x, acc[0][0]); acc[0][1] = ffma2(s0, bp.y, acc[0][1]);
            acc[1][0] = ffma2(s1, bp.x, acc[1][0]); acc[1][1] = ffma2(s1, bp.y, acc[1][1]);
            acc[2][0] = ffma2(s2, bp.x, acc[2][0]); acc[2][1] = ffma2(s2, bp.y, acc[2][1]);
            acc[3][0] = ffma2(s3, bp.x, acc[3][0]); acc[3][1] = ffma2(s3, bp.y, acc[3][1]);
        }
        __syncthreads();
    }

    #pragma unroll
    for (int r = 0; r < 4; r++) {
        float2 p0 = unpack2(acc[r][0]);
        float2 p1 = unpack2(acc[r][1]);
        float4 o; o.x = p0.x; o.y = p0.y; o.z = p1.x; o.w = p1.y;
        *(float4*)&Cbase[(ty * 4 + r) * ldc + tx * 4] = o;
    }
}

// tilde (bid<512): T[m][n][h] = sum_d (Q[m][n*64+d]+vpos[n*64+d]) * Wr[h][n*64+d]
// ac (bid>=512):   AC[m][n][j] = sum_d (Q[m][n*64+d]+upos[n*64+d]) * K[b][j][n*64+d]
__global__ void tac_kernel(const float* __restrict__ Wr,
                           const float* __restrict__ vpos,
                           const float* __restrict__ upos)
{
    const int bid = blockIdx.x;
    if (bid < 512) {
        const int n    = bid >> 6;
        const int rest = bid & 63;
        const int h0   = (rest & 7) * 64;
        const int m0   = (rest >> 3) * 64;
        nt64_body(g_Q + m0 * 512 + n * 64, vpos + n * 64,
                  Wr + h0 * 512 + n * 64,
                  g_T + (m0 * 8 + n) * 512 + h0, 4096);
    } else {
        const int r    = bid - 512;
        const int n    = r >> 5;
        const int rest = r & 31;
        const int j0   = (rest & 3) * 64;
        const int q    = rest >> 2;          // 0..7
        const int b    = q >> 2;
        const int i0   = (q & 3) * 64;
        nt64_body(g_Q + (b * 256 + i0) * 512 + n * 64, upos + n * 64,
                  g_K + (b * 256 + j0) * 512 + n * 64,
                  g_AC + ((b * 256 + i0) * 8 + n) * 256 + j0, 2048);
    }
}

// ---------------- attn: warp-autonomous scores + softmax -> P ----------------
// R13/R10 structure + Treg: 128 threads / 4 warps per CTA, 2 CTAs/SM. Warp w
// owns j in [w*64, w*64+64), 16 groups of 4 j, per-warp cp.async double buffer,
// no block barriers in the mainloop. Lane covers h float4 indices
// {lane + 32t, t=0..3} for all 8 n and 4 j; T slices t=0,1 are held in
// registers (preloaded once), t=2,3 read from smem -> 32 LDS/group not 48.
// Merged butterfly leaves lane L with score (n=L>>2, jj=L&3).
#define JG        4
#define NGRP      16
#define WBUF      (2 * JG * 512)            // 4096 floats per warp (16 KB)
#define OFF_T     (4 * WBUF)                // 16384
#define OFF_SS    (OFF_T + 4096)            // 20480
#define ATTN_SMEM ((OFF_SS + 2080 + 16) * 4)  // 90304 bytes -> 2 CTAs/SM

__device__ __forceinline__ void attn_issue_group(float* mybuf, const float* rowsrc,
                                                 int lane, int g)
{
    float* dst = mybuf + (g & 1) * (JG * 512);
    const int r  = lane >> 3;
    const int c0 = lane & 7;
    const char* src = (const char*)(rowsrc + r * 512);
    uint32_t s = (uint32_t)__cvta_generic_to_shared(dst + r * 512);
    #pragma unroll
    for (int t = 0; t < 16; t++)
        cpasync16(s + (c0 + t * 8) * 16, src + (c0 + t * 8) * 16);
    cpasync_commit();
}

__global__ __launch_bounds__(128, 2)
void attn_kernel(const float* __restrict__ rpe,
                 const int* __restrict__ seq_len,
                 const int* __restrict__ lex_num)
{
    extern __shared__ __align__(16) float smem[];
    float* T_s = smem + OFF_T;
    float* ss  = smem + OFF_SS;
    __shared__ int s_limit;

    const int tid  = threadIdx.x;     // 0..127
    const int m    = blockIdx.x;
    const int b    = m >> 8;
    const int w    = tid >> 5;        // 0..3
    const int lane = tid & 31;
    const int jw   = w * 64;

    const float* rpe_m = rpe + (size_t)m * 256 * 512;
    float* mybuf = smem + w * WBUF;

    attn_issue_group(mybuf, rpe_m + (size_t)(jw + 0 * JG) * 512, lane, 0);
    attn_issue_group(mybuf, rpe_m + (size_t)(jw + 1 * JG) * 512, lane, 1);

    // T rows for this m: 1024 float4, 128 threads x 8
    {
        const float4* src = (const float4*)(g_T + (size_t)m * 4096);
        float4* dst = (float4*)T_s;
        #pragma unroll
        for (int t = 0; t < 8; t++)
            dst[tid + 128 * t] = src[tid + 128 * t];
    }
    if (tid == 0) s_limit = seq_len[b] + lex_num[0];
    __syncthreads();

    // preload T slices t=0,1 into registers (16 LDS.128, once per warp)
    ulonglong2 Treg[8][2];
    #pragma unroll
    for (int n = 0; n < 8; n++) {
        #pragma unroll
        for (int t = 0; t < 2; t++)
            Treg[n][t] = *(const ulonglong2*)(T_s + n * 512 + (lane + t * 32) * 4);
    }

    // ---- mainloop: 16 groups, no block barriers ----
    for (int g = 0; g < NGRP; g++) {
        // ledger: g<15 has one younger group in flight -> wait<1>; g==15 -> wait<0>
        if (g < NGRP - 1) cpasync_wait<1>(); else cpasync_wait<0>();
        __syncwarp();

        const float* rb = mybuf + (g & 1) * (JG * 512);
        unsigned long long acc[32] = {};
        #pragma unroll
        for (int t = 0; t < 4; t++) {
            const int f4 = (lane + t * 32) * 4;
            ulonglong2 rj[JG];
            #pragma unroll
            for (int jj = 0; jj < JG; jj++)
                rj[jj] = *(const ulonglong2*)(rb + jj * 512 + f4);
            #pragma unroll
            for (int n = 0; n < 8; n++) {
                ulonglong2 tv = (t < 2) ? Treg[n][t]
                                        : *(const ulonglong2*)(T_s + n * 512 + f4);
                #pragma unroll
                for (int jj = 0; jj < JG; jj++) {
                    acc[n * 4 + jj] = ffma2(rj[jj].x, tv.x, acc[n * 4 + jj]);
                    acc[n * 4 + jj] = ffma2(rj[jj].y, tv.y, acc[n * 4 + jj]);
                }
            }
        }

        if (g + 2 < NGRP)
            attn_issue_group(mybuf, rpe_m + (size_t)(jw + (g + 2) * JG) * 512, lane, g + 2);

        float v[32];
        #pragma unroll
        for (int i = 0; i < 32; i++) {
            float2 f2 = unpack2(acc[i]);
            v[i] = f2.x + f2.y;
        }
        #pragma unroll
        for (int s = 16; s >= 1; s >>= 1) {
            #pragma unroll
            for (int i = 0; i < 16; i++) {
                if (i < s) {
                    float send = (lane & s) ? v[i] : v[i + s];
                    float keep = (lane & s) ? v[i + s] : v[i];
                    v[i] = keep + __shfl_xor_sync(0xffffffffu, send, s);
                }
            }
        }
        // lane L: n = L>>2, jj = L&3
        ss[(lane >> 2) * 260 + jw + g * JG + (lane & 3)] = v[0];
    }

    __syncthreads();

    // softmax: warp w handles heads w and w+4; fold in AC, scale, mask
    const int limit = s_limit;
    #pragma unroll
    for (int hh = 0; hh < 2; hh++) {
        const int n = w + hh * 4;
        float vals[8];
        #pragma unroll
        for (int t = 0; t < 8; t++) {
            int j = lane + 32 * t;
            float raw = ss[n * 260 + j];
            float ac  = g_AC[((size_t)m * 8 + n) * 256 + j];
            vals[t] = (j < limit) ? (raw + ac) * 0.125f : -1e15f;
        }
        float mx = vals[0];
        #pragma unroll
        for (int t = 1; t < 8; t++) mx = fmaxf(mx, vals[t]);
        #pragma unroll
        for (int o = 16; o; o >>= 1) mx = fmaxf(mx, __shfl_xor_sync(0xffffffffu, mx, o));
        float sum = 0.f;
        #pragma unroll
        for (int t = 0; t < 8; t++) { vals[t] = __expf(vals[t] - mx); sum += vals[t]; }
        #pragma unroll
        for (int o = 16; o; o >>= 1) sum += __shfl_xor_sync(0xffffffffu, sum, o);
        float inv = 1.f / sum;
        #pragma unroll
        for (int t = 0; t < 8; t++) ss[n * 260 + lane + 32 * t] = vals[t] * inv;
    }
    __syncthreads();

    // write P: 512 float4, 128 threads x 4
    {
        float4* P4 = (float4*)g_P + (size_t)m * 512;
        #pragma unroll
        for (int t = 0; t < 4; t++) {
            int f = tid + 128 * t;
            int n = f >> 6;
            int c4 = f & 63;
            P4[f] = *(const float4*)&ss[n * 260 + c4 * 4];
        }
    }
}

// ---------------- ctx: CTX[m][n*64+d] = sum_j P[m][n][j] * V[b][j][n*64+d] ----------------
// R11/R13 best: 32-i tiles, grid (8,8,2), 256 threads, 2x4 microtile, reg prefetch.
__global__ void ctx_kernel()
{
    __shared__ __align__(16) float Ps[64][34];
    __shared__ __align__(16) float Vs[64][68];

    const int tid = threadIdx.x;
    const int tx = tid & 15, ty = tid >> 4;
    const int i0 = blockIdx.x * 32;
    const int n  = blockIdx.y;
    const int b  = blockIdx.z;

    const int li = tid >> 3;            // P: i row 0..31
    const int jq = tid & 7;             // P: 2 float4 per thread (jq, jq+8)
    const int lj = tid >> 2;            // V: j row 0..63
    const int fl = tid & 3;             // V: 4 float4 per thread

    unsigned long long acc[2][2] = {};

    float4 pp[2], vv[4];
    {
        const float* Prow = &g_P[(((size_t)(b * 256 + i0 + li)) * 8 + n) * 256];
        pp[0] = *(const float4*)&Prow[(jq + 0) * 4];
        pp[1] = *(const float4*)&Prow[(jq + 8) * 4];
        const float* Vrow = &g_V[(size_t)(b * 256 + lj) * 512 + n * 64];
        #pragma unroll
        for (int q = 0; q < 4; q++)
            vv[q] = *(const float4*)&Vrow[(fl + q * 4) * 4];
    }

    for (int j0 = 0; j0 < 256; j0 += 64) {
        #pragma unroll
        for (int q = 0; q < 2; q++) {
            int jf = jq + q * 8;
            Ps[jf * 4 + 0][li] = pp[q].x;
            Ps[jf * 4 + 1][li] = pp[q].y;
            Ps[jf * 4 + 2][li] = pp[q].z;
            Ps[jf * 4 + 3][li] = pp[q].w;
        }
        #pragma unroll
        for (int q = 0; q < 4; q++)
            *(float4*)&Vs[lj][(fl + q * 4) * 4] = vv[q];
        __syncthreads();

        if (j0 + 64 < 256) {
            const float* Prow = &g_P[(((size_t)(b * 256 + i0 + li)) * 8 + n) * 256 + j0 + 64];
            pp[0] = *(const float4*)&Prow[(jq + 0) * 4];
            pp[1] = *(const float4*)&Prow[(jq + 8) * 4];
            const float* Vrow = &g_V[(size_t)(b * 256 + j0 + 64 + lj) * 512 + n * 64];
            #pragma unroll
            for (int q = 0; q < 4; q++)
                vv[q] = *(const float4*)&Vrow[(fl + q * 4) * 4];
        }

        #pragma unroll 16
        for (int j = 0; j < 64; j++) {
            float2 av = *(const float2*)&Ps[j][ty * 2];
            ulonglong2 bp = *(const ulonglong2*)&Vs[j][tx * 4];
            unsigned long long s0 = splat2(av.x);
            unsigned long long s1 = splat2(av.y);
            acc[0][0] = ffma2(s0, bp.x, acc[0][0]); acc[0][1] = ffma2(s0, bp.y, acc[0][1]);
            acc[1][0] = ffma2(s1, bp.x, acc[1][0]); acc[1][1] = ffma2(s1, bp.y, acc[1][1]);
        }
        __syncthreads();
    }

    #pragma unroll
    for (int r = 0; r < 2; r++) {
        float2 p0 = unpack2(acc[r][0]);
        float2 p1 = unpack2(acc[r][1]);
        float4 o; o.x = p0.x; o.y = p0.y; o.z = p1.x; o.w = p1.y;
        *(float4*)&g_CTX[(size_t)(b * 256 + i0 + ty * 2 + r) * 512 + n * 64 + tx * 4] = o;
    }
}

// ---------------- launch ----------------
extern "C" void kernel_launch(void* const* d_in, const int* in_sizes, int n_in,
                              void* d_out, int out_size)
{
    const float* key     = (const float*)d_in[0];
    const float* query   = (const float*)d_in[1];
    const float* value   = (const float*)d_in[2];
    const int*   seq_len = (const int*)  d_in[3];
    const int*   lex_num = (const int*)  d_in[4];
    const float* rpe     = (const float*)d_in[7];
    const float* Wk      = (const float*)d_in[8];
    const float* bk      = (const float*)d_in[9];
    const float* Wq      = (const float*)d_in[10];
    const float* bq      = (const float*)d_in[11];
    const float* Wv      = (const float*)d_in[12];
    const float* bv      = (const float*)d_in[13];
    const float* Wr      = (const float*)d_in[14];
    const float* upos    = (const float*)d_in[16];
    const float* vpos    = (const float*)d_in[17];
    const float* Wf      = (const float*)d_in[18];
    const float* bf      = (const float*)d_in[19];
    float* out = (float*)d_out;

    static bool attr_set = false;
    if (!attr_set) {
        cudaFuncSetAttribute(attn_kernel,
                             cudaFuncAttributeMaxDynamicSharedMemorySize, ATTN_SMEM);
        attr_set = true;
    }

    proj_kernel <<<dim3(8, 16, 3), 128>>>(key, query, value, Wk, bk, Wq, bq, Wv, bv);
    tac_kernel  <<<dim3(768), 256>>>(Wr, vpos, upos);
    attn_kernel <<<dim3(BB * LL), 128, ATTN_SMEM>>>(rpe, seq_len, lex_num);
    ctx_kernel  <<<dim3(8, 8, 2), 256>>>();
    final_kernel<<<dim3(8, 16), 128>>>(Wf, bf, out);
}

// round 15
// speedup vs baseline: 1.0367x; 1.0052x over previous
#include <cuda_runtime.h>
#include <cstdint>

#define BB 2
#define LL 256
#define HH 512
#define NHH 8
#define DHH 64

// ---------------- scratch (device globals; no allocation) ----------------
__device__ __align__(16) float g_K[BB*LL*HH];
__device__ __align__(16) float g_Q[BB*LL*HH];
__device__ __align__(16) float g_V[BB*LL*HH];
__device__ __align__(16) float g_T[BB*LL*NHH*HH];    // [m][n][h]  8 MB
__device__ __align__(16) float g_AC[BB*LL*NHH*LL];   // [m][n][j]  4 MB
__device__ __align__(16) float g_P[BB*LL*NHH*LL];    // [m][n][j]  4 MB
__device__ __align__(16) float g_CTX[BB*LL*HH];

// ---------------- f32x2 helpers ----------------
__device__ __forceinline__ unsigned long long ffma2(unsigned long long a,
                                                    unsigned long long b,
                                                    unsigned long long c) {
    unsigned long long d;
    asm("fma.rn.f32x2 %0, %1, %2, %3;" : "=l"(d) : "l"(a), "l"(b), "l"(c));
    return d;
}
__device__ __forceinline__ unsigned long long splat2(float a) {
    unsigned long long r;
    asm("mov.b64 %0, {%1, %1};" : "=l"(r) : "f"(a));
    return r;
}
__device__ __forceinline__ float2 unpack2(unsigned long long v) {
    float2 f;
    asm("mov.b64 {%0, %1}, %2;" : "=f"(f.x), "=f"(f.y) : "l"(v));
    return f;
}
__device__ __forceinline__ void cpasync16(uint32_t s, const void* g) {
    asm volatile("cp.async.cg.shared.global [%0], [%1], 16;\n" :: "r"(s), "l"(g));
}
__device__ __forceinline__ void cpasync_commit() {
    asm volatile("cp.async.commit_group;\n" ::: "memory");
}
template <int N>
__device__ __forceinline__ void cpasync_wait() {
    asm volatile("cp.async.wait_group %0;\n" :: "n"(N) : "memory");
}

// ---------------- 32x64-tile GEMM, 128 threads, 4x4 microtile ----------------
__device__ __forceinline__ void gemm32x64_body(const float* __restrict__ A,
                                               const float* __restrict__ W,
                                               const float* __restrict__ bias,
                                               float* __restrict__ C)
{
    __shared__ __align__(16) float As[32][36];   // [k][m]
    __shared__ __align__(16) float Bs[32][68];   // [k][n]

    const int tid = threadIdx.x;        // 0..127
    const int tx  = tid & 15;
    const int ty  = tid >> 4;
    const int row0 = blockIdx.y * 32;
    const int col0 = blockIdx.x * 64;

    const int lm = tid >> 2;            // A row 0..31
    const int lk = (tid & 3) * 8;       // A k offset
    const int brr = tid >> 4;           // B base row 0..7
    const int bc  = (tid & 15) * 4;     // B col offset

    float4 a0 = *(const float4*)&A[(row0 + lm) * 512 + lk];
    float4 a1 = *(const float4*)&A[(row0 + lm) * 512 + lk + 4];
    float4 b0 = *(const float4*)&W[(brr +  0) * 512 + col0 + bc];
    float4 b1 = *(const float4*)&W[(brr +  8) * 512 + col0 + bc];
    float4 b2 = *(const float4*)&W[(brr + 16) * 512 + col0 + bc];
    float4 b3 = *(const float4*)&W[(brr + 24) * 512 + col0 + bc];

    unsigned long long acc[4][2] = {};

    for (int kt = 0; kt < 512; kt += 32) {
        As[lk + 0][lm] = a0.x; As[lk + 1][lm] = a0.y;
        As[lk + 2][lm] = a0.z; As[lk + 3][lm] = a0.w;
        As[lk + 4][lm] = a1.x; As[lk + 5][lm] = a1.y;
        As[lk + 6][lm] = a1.z; As[lk + 7][lm] = a1.w;
        *(float4*)&Bs[brr +  0][bc] = b0;
        *(float4*)&Bs[brr +  8][bc] = b1;
        *(float4*)&Bs[brr + 16][bc] = b2;
        *(float4*)&Bs[brr + 24][bc] = b3;
        __syncthreads();

        if (kt + 32 < 512) {
            a0 = *(const float4*)&A[(row0 + lm) * 512 + kt + 32 + lk];
            a1 = *(const float4*)&A[(row0 + lm) * 512 + kt + 32 + lk + 4];
            b0 = *(const float4*)&W[(kt + 32 + brr +  0) * 512 + col0 + bc];
            b1 = *(const float4*)&W[(kt + 32 + brr +  8) * 512 + col0 + bc];
            b2 = *(const float4*)&W[(kt + 32 + brr + 16) * 512 + col0 + bc];
            b3 = *(const float4*)&W[(kt + 32 + brr + 24) * 512 + col0 + bc];
        }

        #pragma unroll
        for (int kk = 0; kk < 32; kk++) {
            float4 av = *(const float4*)&As[kk][ty * 4];
            ulonglong2 bp = *(const ulonglong2*)&Bs[kk][tx * 4];
            unsigned long long s0 = splat2(av.x);
            unsigned long long s1 = splat2(av.y);
            unsigned long long s2 = splat2(av.z);
            unsigned long long s3 = splat2(av.w);
            acc[0][0] = ffma2(s0, bp.x, acc[0][0]); acc[0][1] = ffma2(s0, bp.y, acc[0][1]);
            acc[1][0] = ffma2(s1, bp.x, acc[1][0]); acc[1][1] = ffma2(s1, bp.y, acc[1][1]);
            acc[2][0] = ffma2(s2, bp.x, acc[2][0]); acc[2][1] = ffma2(s2, bp.y, acc[2][1]);
            acc[3][0] = ffma2(s3, bp.x, acc[3][0]); acc[3][1] = ffma2(s3, bp.y, acc[3][1]);
        }
        __syncthreads();
    }

    float4 bb = *(const float4*)&bias[col0 + tx * 4];
    #pragma unroll
    for (int r = 0; r < 4; r++) {
        float2 p0 = unpack2(acc[r][0]);
        float2 p1 = unpack2(acc[r][1]);
        float4 o;
        o.x = p0.x + bb.x; o.y = p0.y + bb.y;
        o.z = p1.x + bb.z; o.w = p1.y + bb.w;
        *(float4*)&C[(row0 + ty * 4 + r) * 512 + col0 + tx * 4] = o;
    }
}

__global__ void proj_kernel(const float* __restrict__ key,
                            const float* __restrict__ query,
                            const float* __restrict__ value,
                            const float* __restrict__ Wk, const float* __restrict__ bk,
                            const float* __restrict__ Wq, const float* __restrict__ bq,
                            const float* __restrict__ Wv, const float* __restrict__ bv)
{
    const float *A, *W, *bias;
    float* C;
    if (blockIdx.z == 0)      { A = key;   W = Wk; bias = bk; C = g_K; }
    else if (blockIdx.z == 1) { A = query; W = Wq; bias = bq; C = g_Q; }
    else                      { A = value; W = Wv; bias = bv; C = g_V; }
    gemm32x64_body(A, W, bias, C);
}

__global__ void final_kernel(const float* __restrict__ Wf,
                             const float* __restrict__ bf,
                             float* __restrict__ out)
{
    gemm32x64_body(g_CTX, Wf, bf, out);
}

// ---------------- K=64 A@B^T body (tilde + AC), register-prefetched ----------------
__device__ __forceinline__ void nt64_body(const float* __restrict__ Arow0,
                                          const float* __restrict__ avec,
                                          const float* __restrict__ Brow0,
                                          float* __restrict__ Cbase, int ldc)
{
    __shared__ __align__(16) float As[16][68];
    __shared__ __align__(16) float Bs[16][68];

    const int tid = threadIdx.x;
    const int tx = tid & 15, ty = tid >> 4;
    const int lm = tid >> 2;
    const int lk = (tid & 3) * 4;

    unsigned long long acc[4][2] = {};

    float4 a_n = *(const float4*)&Arow0[lm * 512 + lk];
    float4 b_n = *(const float4*)&Brow0[lm * 512 + lk];

    for (int kt = 0; kt < 64; kt += 16) {
        float4 vb = *(const float4*)&avec[kt + lk];
        As[lk + 0][lm] = a_n.x + vb.x; As[lk + 1][lm] = a_n.y + vb.y;
        As[lk + 2][lm] = a_n.z + vb.z; As[lk + 3][lm] = a_n.w + vb.w;
        Bs[lk + 0][lm] = b_n.x; Bs[lk + 1][lm] = b_n.y;
        Bs[lk + 2][lm] = b_n.z; Bs[lk + 3][lm] = b_n.w;
        __syncthreads();

        if (kt + 16 < 64) {
            a_n = *(const float4*)&Arow0[lm * 512 + kt + 16 + lk];
            b_n = *(const float4*)&Brow0[lm * 512 + kt + 16 + lk];
        }

        #pragma unroll
        for (int kk = 0; kk < 16; kk++) {
            float4 av = *(const float4*)&As[kk][ty * 4];
            ulonglong2 bp = *(const ulonglong2*)&Bs[kk][tx * 4];
            unsigned long long s0 = splat2(av.x);
            unsigned long long s1 = splat2(av.y);
            unsigned long long s2 = splat2(av.z);
            unsigned long long s3 = splat2(av.w);
            acc[0][0] = ffma2(s0, bp.x, acc[0][0]); acc[0][1] = ffma2(s0, bp.y, acc[0][1]);
            acc[1][0] = ffma2(s1, bp.x, acc[1][0]); acc[1][1] = ffma2(s1, bp.y, acc[1][1]);
            acc[2][0] = ffma2(s2, bp.x, acc[2][0]); acc[2][1] = ffma2(s2, bp.y, acc[2][1]);
            acc[3][0] = ffma2(s3, bp.x, acc[3][0]); acc[3][1] = ffma2(s3, bp.y, acc[3][1]);
        }
        __syncthreads();
    }

    #pragma unroll
    for (int r = 0; r < 4; r++) {
        float2 p0 = unpack2(acc[r][0]);
        float2 p1 = unpack2(acc[r][1]);
        float4 o; o.x = p0.x; o.y = p0.y; o.z = p1.x; o.w = p1.y;
        *(float4*)&Cbase[(ty * 4 + r) * ldc + tx * 4] = o;
    }
}

// tilde (bid<512): T[m][n][h] = sum_d (Q[m][n*64+d]+vpos[n*64+d]) * Wr[h][n*64+d]
// ac (bid>=512):   AC[m][n][j] = sum_d (Q[m][n*64+d]+upos[n*64+d]) * K[b][j][n*64+d]
__global__ void tac_kernel(const float* __restrict__ Wr,
                           const float* __restrict__ vpos,
                           const float* __restrict__ upos)
{
    const int bid = blockIdx.x;
    if (bid < 512) {
        const int n    = bid >> 6;
        const int rest = bid & 63;
        const int h0   = (rest & 7) * 64;
        const int m0   = (rest >> 3) * 64;
        nt64_body(g_Q + m0 * 512 + n * 64, vpos + n * 64,
                  Wr + h0 * 512 + n * 64,
                  g_T + (m0 * 8 + n) * 512 + h0, 4096);
    } else {
        const int r    = bid - 512;
        const int n    = r >> 5;
        const int rest = r & 31;
        const int j0   = (rest & 3) * 64;
        const int q    = rest >> 2;          // 0..7
        const int b    = q >> 2;
        const int i0   = (q & 3) * 64;
        nt64_body(g_Q + (b * 256 + i0) * 512 + n * 64, upos + n * 64,
                  g_K + (b * 256 + j0) * 512 + n * 64,
                  g_AC + ((b * 256 + i0) * 8 + n) * 256 + j0, 2048);
    }
}

// ---------------- attn: warp-autonomous scores + softmax -> P ----------------
// R14 structure + FULL Treg: 128 threads / 4 warps per CTA, 2 CTAs/SM. Warp w
// owns j in [w*64, w*64+64), 16 groups of 4 j, per-warp cp.async double buffer,
// no block barriers in the mainloop. Lane covers h float4 indices
// {lane + 32t, t=0..3} for all 8 n and 4 j; ALL T slices held in registers
// (Treg[8][4], preloaded once) -> mainloop LDS = 16 rpe loads only.
// Merged butterfly leaves lane L with score (n=L>>2, jj=L&3).
#define JG        4
#define NGRP      16
#define WBUF      (2 * JG * 512)            // 4096 floats per warp (16 KB)
#define OFF_T     (4 * WBUF)                // 16384
#define OFF_SS    (OFF_T + 4096)            // 20480
#define ATTN_SMEM ((OFF_SS + 2080 + 16) * 4)  // 90304 bytes -> 2 CTAs/SM

__device__ __forceinline__ void attn_issue_group(float* mybuf, const float* rowsrc,
                                                 int lane, int g)
{
    float* dst = mybuf + (g & 1) * (JG * 512);
    const int r  = lane >> 3;
    const int c0 = lane & 7;
    const char* src = (const char*)(rowsrc + r * 512);
    uint32_t s = (uint32_t)__cvta_generic_to_shared(dst + r * 512);
    #pragma unroll
    for (int t = 0; t < 16; t++)
        cpasync16(s + (c0 + t * 8) * 16, src + (c0 + t * 8) * 16);
    cpasync_commit();
}

__global__ __launch_bounds__(128, 2)
void attn_kernel(const float* __restrict__ rpe,
                 const int* __restrict__ seq_len,
                 const int* __restrict__ lex_num)
{
    extern __shared__ __align__(16) float smem[];
    float* T_s = smem + OFF_T;
    float* ss  = smem + OFF_SS;
    __shared__ int s_limit;

    const int tid  = threadIdx.x;     // 0..127
    const int m    = blockIdx.x;
    const int b    = m >> 8;
    const int w    = tid >> 5;        // 0..3
    const int lane = tid & 31;
    const int jw   = w * 64;

    const float* rpe_m = rpe + (size_t)m * 256 * 512;
    float* mybuf = smem + w * WBUF;

    attn_issue_group(mybuf, rpe_m + (size_t)(jw + 0 * JG) * 512, lane, 0);
    attn_issue_group(mybuf, rpe_m + (size_t)(jw + 1 * JG) * 512, lane, 1);

    // T rows for this m: 1024 float4, 128 threads x 8
    {
        const float4* src = (const float4*)(g_T + (size_t)m * 4096);
        float4* dst = (float4*)T_s;
        #pragma unroll
        for (int t = 0; t < 8; t++)
            dst[tid + 128 * t] = src[tid + 128 * t];
    }
    if (tid == 0) s_limit = seq_len[b] + lex_num[0];
    __syncthreads();

    // preload ALL T slices into registers (32 LDS.128, once per warp)
    ulonglong2 Treg[8][4];
    #pragma unroll
    for (int n = 0; n < 8; n++) {
        #pragma unroll
        for (int t = 0; t < 4; t++)
            Treg[n][t] = *(const ulonglong2*)(T_s + n * 512 + (lane + t * 32) * 4);
    }

    // ---- mainloop: 16 groups, no block barriers ----
    for (int g = 0; g < NGRP; g++) {
        // ledger: g<15 has one younger group in flight -> wait<1>; g==15 -> wait<0>
        if (g < NGRP - 1) cpasync_wait<1>(); else cpasync_wait<0>();
        __syncwarp();

        const float* rb = mybuf + (g & 1) * (JG * 512);
        unsigned long long acc[32] = {};
        #pragma unroll
        for (int t = 0; t < 4; t++) {
            const int f4 = (lane + t * 32) * 4;
            ulonglong2 rj[JG];
            #pragma unroll
            for (int jj = 0; jj < JG; jj++)
                rj[jj] = *(const ulonglong2*)(rb + jj * 512 + f4);
            #pragma unroll
            for (int n = 0; n < 8; n++) {
                ulonglong2 tv = Treg[n][t];
                #pragma unroll
                for (int jj = 0; jj < JG; jj++) {
                    acc[n * 4 + jj] = ffma2(rj[jj].x, tv.x, acc[n * 4 + jj]);
                    acc[n * 4 + jj] = ffma2(rj[jj].y, tv.y, acc[n * 4 + jj]);
                }
            }
        }

        if (g + 2 < NGRP)
            attn_issue_group(mybuf, rpe_m + (size_t)(jw + (g + 2) * JG) * 512, lane, g + 2);

        float v[32];
        #pragma unroll
        for (int i = 0; i < 32; i++) {
            float2 f2 = unpack2(acc[i]);
            v[i] = f2.x + f2.y;
        }
        #pragma unroll
        for (int s = 16; s >= 1; s >>= 1) {
            #pragma unroll
            for (int i = 0; i < 16; i++) {
                if (i < s) {
                    float send = (lane & s) ? v[i] : v[i + s];
                    float keep = (lane & s) ? v[i + s] : v[i];
                    v[i] = keep + __shfl_xor_sync(0xffffffffu, send, s);
                }
            }
        }
        // lane L: n = L>>2, jj = L&3
        ss[(lane >> 2) * 260 + jw + g * JG + (lane & 3)] = v[0];
    }

    __syncthreads();

    // softmax: warp w handles heads w and w+4; fold in AC, scale, mask
    const int limit = s_limit;
    #pragma unroll
    for (int hh = 0; hh < 2; hh++) {
        const int n = w + hh * 4;
        float vals[8];
        #pragma unroll
        for (int t = 0; t < 8; t++) {
            int j = lane + 32 * t;
            float raw = ss[n * 260 + j];
            float ac  = g_AC[((size_t)m * 8 + n) * 256 + j];
            vals[t] = (j < limit) ? (raw + ac) * 0.125f : -1e15f;
        }
        float mx = vals[0];
        #pragma unroll
        for (int t = 1; t < 8; t++) mx = fmaxf(mx, vals[t]);
        #pragma unroll
        for (int o = 16; o; o >>= 1) mx = fmaxf(mx, __shfl_xor_sync(0xffffffffu, mx, o));
        float sum = 0.f;
        #pragma unroll
        for (int t = 0; t < 8; t++) { vals[t] = __expf(vals[t] - mx); sum += vals[t]; }
        #pragma unroll
        for (int o = 16; o; o >>= 1) sum += __shfl_xor_sync(0xffffffffu, sum, o);
        float inv = 1.f / sum;
        #pragma unroll
        for (int t = 0; t < 8; t++) ss[n * 260 + lane + 32 * t] = vals[t] * inv;
    }
    __syncthreads();

    // write P: 512 float4, 128 threads x 4
    {
        float4* P4 = (float4*)g_P + (size_t)m * 512;
        #pragma unroll
        for (int t = 0; t < 4; t++) {
            int f = tid + 128 * t;
            int n = f >> 6;
            int c4 = f & 63;
            P4[f] = *(const float4*)&ss[n * 260 + c4 * 4];
        }
    }
}

// ---------------- ctx: CTX[m][n*64+d] = sum_j P[m][n][j] * V[b][j][n*64+d] ----------------
// R11/R13 best: 32-i tiles, grid (8,8,2), 256 threads, 2x4 microtile, reg prefetch.
__global__ void ctx_kernel()
{
    __shared__ __align__(16) float Ps[64][34];
    __shared__ __align__(16) float Vs[64][68];

    const int tid = threadIdx.x;
    const int tx = tid & 15, ty = tid >> 4;
    const int i0 = blockIdx.x * 32;
    const int n  = blockIdx.y;
    const int b  = blockIdx.z;

    const int li = tid >> 3;            // P: i row 0..31
    const int jq = tid & 7;             // P: 2 float4 per thread (jq, jq+8)
    const int lj = tid >> 2;            // V: j row 0..63
    const int fl = tid & 3;             // V: 4 float4 per thread

    unsigned long long acc[2][2] = {};

    float4 pp[2], vv[4];
    {
        const float* Prow = &g_P[(((size_t)(b * 256 + i0 + li)) * 8 + n) * 256];
        pp[0] = *(const float4*)&Prow[(jq + 0) * 4];
        pp[1] = *(const float4*)&Prow[(jq + 8) * 4];
        const float* Vrow = &g_V[(size_t)(b * 256 + lj) * 512 + n * 64];
        #pragma unroll
        for (int q = 0; q < 4; q++)
            vv[q] = *(const float4*)&Vrow[(fl + q * 4) * 4];
    }

    for (int j0 = 0; j0 < 256; j0 += 64) {
        #pragma unroll
        for (int q = 0; q < 2; q++) {
            int jf = jq + q * 8;
            Ps[jf * 4 + 0][li] = pp[q].x;
            Ps[jf * 4 + 1][li] = pp[q].y;
            Ps[jf * 4 + 2][li] = pp[q].z;
            Ps[jf * 4 + 3][li] = pp[q].w;
        }
        #pragma unroll
        for (int q = 0; q < 4; q++)
            *(float4*)&Vs[lj][(fl + q * 4) * 4] = vv[q];
        __syncthreads();

        if (j0 + 64 < 256) {
            const float* Prow = &g_P[(((size_t)(b * 256 + i0 + li)) * 8 + n) * 256 + j0 + 64];
            pp[0] = *(const float4*)&Prow[(jq + 0) * 4];
            pp[1] = *(const float4*)&Prow[(jq + 8) * 4];
            const float* Vrow = &g_V[(size_t)(b * 256 + j0 + 64 + lj) * 512 + n * 64];
            #pragma unroll
            for (int q = 0; q < 4; q++)
                vv[q] = *(const float4*)&Vrow[(fl + q * 4) * 4];
        }

        #pragma unroll 16
        for (int j = 0; j < 64; j++) {
            float2 av = *(const float2*)&Ps[j][ty * 2];
            ulonglong2 bp = *(const ulonglong2*)&Vs[j][tx * 4];
            unsigned long long s0 = splat2(av.x);
            unsigned long long s1 = splat2(av.y);
            acc[0][0] = ffma2(s0, bp.x, acc[0][0]); acc[0][1] = ffma2(s0, bp.y, acc[0][1]);
            acc[1][0] = ffma2(s1, bp.x, acc[1][0]); acc[1][1] = ffma2(s1, bp.y, acc[1][1]);
        }
        __syncthreads();
    }

    #pragma unroll
    for (int r = 0; r < 2; r++) {
        float2 p0 = unpack2(acc[r][0]);
        float2 p1 = unpack2(acc[r][1]);
        float4 o; o.x = p0.x; o.y = p0.y; o.z = p1.x; o.w = p1.y;
        *(float4*)&g_CTX[(size_t)(b * 256 + i0 + ty * 2 + r) * 512 + n * 64 + tx * 4] = o;
    }
}

// ---------------- launch ----------------
extern "C" void kernel_launch(void* const* d_in, const int* in_sizes, int n_in,
                              void* d_out, int out_size)
{
    const float* key     = (const float*)d_in[0];
    const float* query   = (const float*)d_in[1];
    const float* value   = (const float*)d_in[2];
    const int*   seq_len = (const int*)  d_in[3];
    const int*   lex_num = (const int*)  d_in[4];
    const float* rpe     = (const float*)d_in[7];
    const float* Wk      = (const float*)d_in[8];
    const float* bk      = (const float*)d_in[9];
    const float* Wq      = (const float*)d_in[10];
    const float* bq      = (const float*)d_in[11];
    const float* Wv      = (const float*)d_in[12];
    const float* bv      = (const float*)d_in[13];
    const float* Wr      = (const float*)d_in[14];
    const float* upos    = (const float*)d_in[16];
    const float* vpos    = (const float*)d_in[17];
    const float* Wf      = (const float*)d_in[18];
    const float* bf      = (const float*)d_in[19];
    float* out = (float*)d_out;

    static bool attr_set = false;
    if (!attr_set) {
        cudaFuncSetAttribute(attn_kernel,
                             cudaFuncAttributeMaxDynamicSharedMemorySize, ATTN_SMEM);
        attr_set = true;
    }

    proj_kernel <<<dim3(8, 16, 3), 128>>>(key, query, value, Wk, bk, Wq, bq, Wv, bv);
    tac_kernel  <<<dim3(768), 256>>>(Wr, vpos, upos);
    attn_kernel <<<dim3(BB * LL), 128, ATTN_SMEM>>>(rpe, seq_len, lex_num);
    ctx_kernel  <<<dim3(8, 8, 2), 256>>>();
    final_kernel<<<dim3(8, 16), 128>>>(Wf, bf, out);
}